// round 13
// baseline (speedup 1.0000x reference)
#include <cuda_runtime.h>
#include <cuda_bf16.h>
#include <cstdint>

// Problem constants (fixed by setup_inputs)
#define NB 16      // batch
#define LL 512     // sequence length
#define DD 256     // encoder dim = filter size
#define TT 4096    // WVF_max_length
#define TP 32      // L-positions per conv block (16 Winograd F(2,3) groups)
#define NG 16      // groups per block

// Intermediates (no cudaMalloc allowed) — referenced directly from device code.
__device__ float g_h1[NB * LL * DD];
__device__ int   g_dur[NB * LL];
__device__ int   g_lmap[NB * TT];
// Winograd-transformed, pair-packed weights per layer:
//   gp[d*256+f]          = (g0,g1)   (g0=w0, g1=(w0+w1+w2)/2)
//   gp[65536 + d*256+f]  = (g2,g3)   (g2=(w0-w1+w2)/2, g3=w2)
// f fastest -> LDG.64 with 8B lane stride, fully coalesced.
__device__ unsigned long long g_gp1[2 * DD * 256];
__device__ unsigned long long g_gp2[2 * DD * 256];

// ---- packed fp32x2 helpers (sm_100a; ptxas never auto-emits FFMA2) ----
__device__ __forceinline__ void fma2(unsigned long long& acc,
                                     unsigned long long a,
                                     unsigned long long b)
{
    asm("fma.rn.f32x2 %0, %1, %2, %0;" : "+l"(acc) : "l"(a), "l"(b));
}
__device__ __forceinline__ unsigned long long pack2(float a, float b)
{
    unsigned long long r;
    asm("mov.b64 %0, {%1, %2};" : "=l"(r) : "f"(a), "f"(b));
    return r;
}
__device__ __forceinline__ float2 unpack2(unsigned long long v)
{
    float2 r;
    asm("mov.b64 {%0, %1}, %2;" : "=f"(r.x), "=f"(r.y) : "l"(v));
    return r;
}

// ---------------------------------------------------------------------------
// Weight transform + pack: w[k][d][f] -> Winograd g components, pair-packed.
// grid 512 = layer*256 + d, 256 threads (one per f).
// ---------------------------------------------------------------------------
__global__ void __launch_bounds__(256) pack_w_kernel(
    const float* __restrict__ w1, const float* __restrict__ w2)
{
    const int b = blockIdx.x;
    const int layer = b >> 8;
    const int d = b & 255;
    const int f = threadIdx.x;
    const float* src = (layer == 0) ? w1 : w2;
    unsigned long long* dst = (layer == 0) ? g_gp1 : g_gp2;
    const float w0 = src[0 * (DD * 256) + d * 256 + f];
    const float wm = src[1 * (DD * 256) + d * 256 + f];
    const float w2v = src[2 * (DD * 256) + d * 256 + f];
    const float s = 0.5f * (w0 + w2v);
    dst[d * 256 + f]              = pack2(w0, s + 0.5f * wm);       // (g0, g1)
    dst[DD * 256 + d * 256 + f]   = pack2(s - 0.5f * wm, w2v);      // (g2, g3)
}

// ---------------------------------------------------------------------------
// Fused Winograd-F(2,3) conv1d(K=3, same pad) + bias + LayerNorm(F) + ReLU
// STAGE 0: src = x, gp = g_gp1, writes h to g_h1.
// STAGE 1: src = g_h1, gp = g_gp2, fuses the final linear + duration:
//          dur[n,l] = int(relu(h.lin_w + lin_b) + 0.5) — h2 never hits gmem.
// One block = 32 L-positions = 16 groups, 256 threads (one per channel f).
// Mainloop uses the R9 discipline: unroll 2, in-body weight loads -> ptxas
// software-pipelines next-step LDGs under current-step FMAs.
// Dynamic smem (100352 B): zp0[16][256] ull | zp1[16][256] ull | xs[34][256] f32
// xs region reused as the LN tile after the transform.
// ---------------------------------------------------------------------------
#define SMEM_BYTES (2 * NG * DD * 8 + (TP + 2) * DD * 4)   // 65536 + 34816

template<int STAGE>
__global__ void __launch_bounds__(256, 2) conv_ln_relu_kernel(
    const float* __restrict__ x,
    const float* __restrict__ bias,
    const float* __restrict__ gamma,
    const float* __restrict__ beta,
    const float* __restrict__ lin_w,
    const float* __restrict__ lin_b)
{
    extern __shared__ char smem_raw[];
    unsigned long long* zp0 = (unsigned long long*)smem_raw;            // [NG][256]
    unsigned long long* zp1 = zp0 + NG * DD;                            // [NG][256]
    float (*xs)[DD] = (float(*)[DD])(smem_raw + 2 * NG * DD * 8);       // [34][256]
    __shared__ float mu_s[TP];
    __shared__ float rs_s[TP];

    const float* __restrict__ src = (STAGE == 0) ? x : (const float*)g_h1;
    const unsigned long long* __restrict__ gp =
        (STAGE == 0) ? (const unsigned long long*)g_gp1
                     : (const unsigned long long*)g_gp2;

    const int blk = blockIdx.x;
    const int n   = blk / (LL / TP);
    const int l0  = (blk % (LL / TP)) * TP;
    const int f   = threadIdx.x;

    // Load input rows (zero padding at sequence edges)
    #pragma unroll
    for (int r = 0; r < TP + 2; r++) {
        int l = l0 - 1 + r;
        xs[r][f] = (l >= 0 && l < LL) ? src[(n * LL + l) * DD + f] : 0.f;
    }
    __syncthreads();

    // Winograd input transform per group g (outputs p=2g, 2g+1):
    // x0..x3 = xs[2g..2g+3];  zp0=(x0-x2, x1+x2), zp1=(x2-x1, x1-x3)
    #pragma unroll
    for (int g = 0; g < NG; g++) {
        const float x0 = xs[2 * g + 0][f];
        const float x1 = xs[2 * g + 1][f];
        const float x2 = xs[2 * g + 2][f];
        const float x3 = xs[2 * g + 3][f];
        zp0[g * DD + f] = pack2(x0 - x2, x1 + x2);
        zp1[g * DD + f] = pack2(x2 - x1, x1 - x3);
    }
    __syncthreads();

    // m01[g] = (Σ_d z0*g0, Σ_d z1*g1);  m23[g] = (Σ_d z2*g2, Σ_d z3*g3)
    unsigned long long m01[NG], m23[NG];
    #pragma unroll
    for (int g = 0; g < NG; g++) { m01[g] = 0ull; m23[g] = 0ull; }

    const unsigned long long* gp01 = gp + f;
    const unsigned long long* gp23 = gp + DD * 256 + f;

    // Mainloop: d in steps of 4, unrolled 2x by ptxas (R9 discipline).
    // Per step: 8 coalesced LDG.64 (weights), 64 LDS.128 (broadcast), 128 FFMA2.
    #pragma unroll 2
    for (int d = 0; d < DD; d += 4) {
        unsigned long long w01[4], w23[4];
        #pragma unroll
        for (int j = 0; j < 4; j++) {
            w01[j] = gp01[(d + j) * 256];
            w23[j] = gp23[(d + j) * 256];
        }
        #pragma unroll
        for (int g = 0; g < NG; g++) {
            const ulonglong2 a0 = *(const ulonglong2*)&zp0[g * DD + d];
            const ulonglong2 a1 = *(const ulonglong2*)&zp0[g * DD + d + 2];
            const ulonglong2 b0 = *(const ulonglong2*)&zp1[g * DD + d];
            const ulonglong2 b1 = *(const ulonglong2*)&zp1[g * DD + d + 2];
            fma2(m01[g], a0.x, w01[0]);
            fma2(m01[g], a0.y, w01[1]);
            fma2(m01[g], a1.x, w01[2]);
            fma2(m01[g], a1.y, w01[3]);
            fma2(m23[g], b0.x, w23[0]);
            fma2(m23[g], b0.y, w23[1]);
            fma2(m23[g], b1.x, w23[2]);
            fma2(m23[g], b1.y, w23[3]);
        }
    }
    __syncthreads();   // zp/xs reads done; reuse xs region as the h tile

    float (*hs)[DD] = xs;

    // Inverse transform + bias: y0 = m0+m1+m2, y1 = m1-m2-m3
    float acc[TP];
    {
        const float bf = bias[f];
        #pragma unroll
        for (int g = 0; g < NG; g++) {
            const float2 u = unpack2(m01[g]);
            const float2 v = unpack2(m23[g]);
            acc[2 * g + 0] = u.x + u.y + v.x + bf;
            acc[2 * g + 1] = u.y - v.x - v.y + bf;
            hs[2 * g + 0][f] = acc[2 * g + 0];
            hs[2 * g + 1][f] = acc[2 * g + 1];
        }
    }
    __syncthreads();

    // LayerNorm over f (256) per position p: warp-parallel reductions
    {
        const int wid = f >> 5, lane = f & 31;
        #pragma unroll
        for (int rr = 0; rr < 4; rr++) {
            int r = wid * 4 + rr;
            float s = 0.f, s2 = 0.f;
            #pragma unroll
            for (int c0 = 0; c0 < 256; c0 += 32) {
                float v = hs[r][c0 + lane];
                s += v; s2 += v * v;
            }
            #pragma unroll
            for (int o = 16; o; o >>= 1) {
                s  += __shfl_xor_sync(0xFFFFFFFFu, s,  o);
                s2 += __shfl_xor_sync(0xFFFFFFFFu, s2, o);
            }
            if (lane == 0) {
                float mu = s * (1.f / 256.f);
                float var = s2 * (1.f / 256.f) - mu * mu;
                mu_s[r] = mu;
                rs_s[r] = rsqrtf(var + 1e-5f);
            }
        }
    }
    __syncthreads();

    if (STAGE == 0) {
        const float gg = gamma[f], bb = beta[f];
        #pragma unroll
        for (int p = 0; p < TP; p++) {
            float v = (acc[p] - mu_s[p]) * rs_s[p] * gg + bb;
            g_h1[(n * LL + l0 + p) * 256 + f] = fmaxf(v, 0.f);
        }
    } else {
        // Fused linear head: prod[p][f] = relu(LN(h)) * lin_w[f], reduce over f.
        const float gg = gamma[f], bb = beta[f];
        const float lw = lin_w[f];
        #pragma unroll
        for (int p = 0; p < TP; p++) {
            float v = fmaxf((acc[p] - mu_s[p]) * rs_s[p] * gg + bb, 0.f);
            hs[p][f] = v * lw;
        }
        __syncthreads();
        {
            const int wid = f >> 5, lane = f & 31;
            const float lb = lin_b[0];
            #pragma unroll
            for (int rr = 0; rr < 4; rr++) {
                int r = wid * 4 + rr;
                float s = 0.f;
                #pragma unroll
                for (int c0 = 0; c0 < 256; c0 += 32)
                    s += hs[r][c0 + lane];
                #pragma unroll
                for (int o = 16; o; o >>= 1)
                    s += __shfl_xor_sync(0xFFFFFFFFu, s, o);
                if (lane == 0) {
                    float dpo = fmaxf(s + lb, 0.f);
                    g_dur[n * LL + l0 + r] = (int)(dpo + 0.5f);
                }
            }
        }
    }
}

// ---------------------------------------------------------------------------
// Inclusive scan of durations per row + t -> l binary-search map.
// ---------------------------------------------------------------------------
__global__ void __launch_bounds__(512) scan_map_kernel()
{
    const int n = blockIdx.x;
    const int l = threadIdx.x;

    __shared__ int sc[LL];
    sc[l] = g_dur[n * LL + l];
    __syncthreads();
    for (int off = 1; off < LL; off <<= 1) {
        int v = (l >= off) ? sc[l - off] : 0;
        __syncthreads();
        sc[l] += v;
        __syncthreads();
    }

    const int total = sc[LL - 1];
    for (int t = l; t < TT; t += LL) {
        int res = -1;
        if (t < total) {
            int lo = 0, hi = LL - 1;
            while (lo < hi) {
                int mid = (lo + hi) >> 1;
                if (sc[mid] > t) hi = mid; else lo = mid + 1;
            }
            res = lo;
        }
        g_lmap[n * TT + t] = res;
    }
}

// ---------------------------------------------------------------------------
// out[n, t, :] = x[n, lmap[n,t], :]  (or zeros), grid-stride (8 float4/thread)
// + fused tail (WVF_pos = 1..TT) handling. 2048 blocks.
// ---------------------------------------------------------------------------
#define EXP_BLOCKS 2048
__global__ void __launch_bounds__(256) expand_copy_kernel(
    const float* __restrict__ x,
    float* __restrict__ out,
    int tail)
{
    const int nthreads = EXP_BLOCKS * 256;
    const int tid0 = blockIdx.x * 256 + threadIdx.x;

    #pragma unroll
    for (int k = 0; k < 8; k++) {
        const int idx = tid0 + k * nthreads;       // over NB*TT*64 float4
        const int c = idx & 63;
        const int t = (idx >> 6) & (TT - 1);
        const int n = idx >> 18;
        const int l = g_lmap[n * TT + t];
        float4 v = make_float4(0.f, 0.f, 0.f, 0.f);
        if (l >= 0) v = ((const float4*)x)[(n * LL + l) * (DD / 4) + c];
        ((float4*)out)[idx] = v;
    }

    // Fused tail: out[NB*TT*DD + i] = (i % TT) + 1
    for (int i = tid0; i < tail; i += nthreads)
        out[NB * TT * DD + i] = (float)((i % TT) + 1);
}

extern "C" void kernel_launch(void* const* d_in, const int* in_sizes, int n_in,
                              void* d_out, int out_size)
{
    const float* x       = (const float*)d_in[0];
    const float* conv1_w = (const float*)d_in[1];
    const float* conv1_b = (const float*)d_in[2];
    const float* ln1_g   = (const float*)d_in[3];
    const float* ln1_b   = (const float*)d_in[4];
    const float* conv2_w = (const float*)d_in[5];
    const float* conv2_b = (const float*)d_in[6];
    const float* ln2_g   = (const float*)d_in[7];
    const float* ln2_b   = (const float*)d_in[8];
    const float* lin_w   = (const float*)d_in[9];
    const float* lin_b   = (const float*)d_in[10];

    float* out = (float*)d_out;

    // Opt-in to >48KB dynamic smem (idempotent; not an allocation; capture-safe).
    static bool attr_done = false;
    if (!attr_done) {
        cudaFuncSetAttribute(conv_ln_relu_kernel<0>,
                             cudaFuncAttributeMaxDynamicSharedMemorySize, SMEM_BYTES);
        cudaFuncSetAttribute(conv_ln_relu_kernel<1>,
                             cudaFuncAttributeMaxDynamicSharedMemorySize, SMEM_BYTES);
        attr_done = true;
    }

    pack_w_kernel<<<2 * DD, 256>>>(conv1_w, conv2_w);

    const int conv_grid = NB * (LL / TP);   // 256
    conv_ln_relu_kernel<0><<<conv_grid, 256, SMEM_BYTES>>>(x, conv1_b, ln1_g, ln1_b, lin_w, lin_b);
    conv_ln_relu_kernel<1><<<conv_grid, 256, SMEM_BYTES>>>(x, conv2_b, ln2_g, ln2_b, lin_w, lin_b);
    scan_map_kernel<<<NB, LL>>>();

    const int main_elems = NB * TT * DD;
    int tail = out_size - main_elems;
    if (tail < 0) tail = 0;
    expand_copy_kernel<<<EXP_BLOCKS, 256>>>(x, out, tail);
}

// round 14
// speedup vs baseline: 1.5086x; 1.5086x over previous
#include <cuda_runtime.h>
#include <cuda_bf16.h>
#include <cstdint>

// Problem constants (fixed by setup_inputs)
#define NB 16      // batch
#define LL 512     // sequence length
#define DD 256     // encoder dim = filter size
#define TT 4096    // WVF_max_length
#define TP 32      // L-positions per conv block
#define XSS 260    // xs smem row stride (pad: 260%32=4 -> conflict-free frags)

// Intermediates (no cudaMalloc allowed) — referenced directly from device code.
__device__ float g_xhi[NB * LL * DD];   // tf32-hi of x
__device__ float g_xlo[NB * LL * DD];   // tf32-lo of x
__device__ float g_h1hi[NB * LL * DD];  // tf32-hi of h1
__device__ float g_h1lo[NB * LL * DD];  // tf32-lo of h1
__device__ int   g_dur[NB * LL];
__device__ int   g_lmap[NB * TT];
// Fragment-packed weights: [kk][c][tile][lane] float4 = (bhi0,bhi1,blo0,blo1)
//   b0 = w[kk][8c + lane%4    ][8*tile + lane/4]
//   b1 = w[kk][8c + lane%4 + 4][8*tile + lane/4]
__device__ float4 g_wf1[3 * 32 * 32 * 32];
__device__ float4 g_wf2[3 * 32 * 32 * 32];

// ---- tf32 helpers ----
__device__ __forceinline__ unsigned f2tf32(float v)
{
    unsigned r;
    asm("cvt.rna.tf32.f32 %0, %1;" : "=r"(r) : "f"(v));
    return r;
}

// m16n8k8 tf32 MMA, C += A*B (C in-place)
__device__ __forceinline__ void mma_tf32(float* c,
                                         unsigned a0, unsigned a1,
                                         unsigned a2, unsigned a3,
                                         unsigned b0, unsigned b1)
{
    asm("mma.sync.aligned.m16n8k8.row.col.f32.tf32.tf32.f32 "
        "{%0,%1,%2,%3},{%4,%5,%6,%7},{%8,%9},{%0,%1,%2,%3};"
        : "+f"(c[0]), "+f"(c[1]), "+f"(c[2]), "+f"(c[3])
        : "r"(a0), "r"(a1), "r"(a2), "r"(a3), "r"(b0), "r"(b1));
}

// ---------------------------------------------------------------------------
// Prep: split x into tf32 hi/lo tensors.
// ---------------------------------------------------------------------------
__global__ void __launch_bounds__(1024) prep_x_kernel(const float* __restrict__ x)
{
    const int i = blockIdx.x * 1024 + threadIdx.x;   // grid covers NB*LL*DD
    const float v = x[i];
    const unsigned hb = f2tf32(v);
    const float hf = __uint_as_float(hb);
    const unsigned lb = f2tf32(v - hf);
    g_xhi[i] = hf;
    g_xlo[i] = __uint_as_float(lb);
}

// ---------------------------------------------------------------------------
// Prep: pack weights into B-fragment order with tf32 hi/lo.
// grid = 2 layers * 3 kk * 32 c;  block = 1024 (tile = tid/32, lane = tid%32)
// ---------------------------------------------------------------------------
__global__ void __launch_bounds__(1024) pack_wf_kernel(
    const float* __restrict__ w1, const float* __restrict__ w2)
{
    const int b = blockIdx.x;
    const int layer = b / 96;
    const int kk = (b % 96) / 32;
    const int c = b % 32;
    const int tile = threadIdx.x >> 5;
    const int lane = threadIdx.x & 31;
    const int t = lane & 3;
    const int g = lane >> 2;
    const int f = tile * 8 + g;
    const float* src = (layer == 0) ? w1 : w2;
    float4* dst = (layer == 0) ? g_wf1 : g_wf2;

    const float w0 = src[kk * (DD * 256) + (8 * c + t) * 256 + f];
    const float w1v = src[kk * (DD * 256) + (8 * c + t + 4) * 256 + f];
    const unsigned h0 = f2tf32(w0);
    const unsigned h1 = f2tf32(w1v);
    const unsigned l0 = f2tf32(w0 - __uint_as_float(h0));
    const unsigned l1 = f2tf32(w1v - __uint_as_float(h1));
    dst[((kk * 32 + c) * 32 + tile) * 32 + lane] =
        make_float4(__uint_as_float(h0), __uint_as_float(h1),
                    __uint_as_float(l0), __uint_as_float(l1));
}

// ---------------------------------------------------------------------------
// Fused conv1d(K=3) via 3xTF32 warp-MMA + bias + LayerNorm(F) + ReLU
// STAGE 0: src = g_xhi/g_xlo,  dst = g_h1hi/g_h1lo (hi/lo of relu(LN(conv)))
// STAGE 1: src = g_h1hi/g_h1lo, fused linear head -> g_dur
// Block = 32 l x 256 f, 8 warps: wl = wid>>2 (16-l subtile), wf = wid&3 (64-f).
// Dynamic smem: xs_hi[34][260] | xs_lo[34][260]; hs (32x256) aliases xs_hi.
// ---------------------------------------------------------------------------
#define SMEM_BYTES (2 * 34 * XSS * 4)   // 70720

template<int STAGE>
__global__ void __launch_bounds__(256, 2) conv_ln_relu_kernel(
    const float* __restrict__ bias,
    const float* __restrict__ gamma,
    const float* __restrict__ beta,
    const float* __restrict__ lin_w,
    const float* __restrict__ lin_b)
{
    extern __shared__ float smem[];
    float* xs_hi = smem;                  // [34][XSS]
    float* xs_lo = smem + 34 * XSS;       // [34][XSS]
    float* hs    = smem;                  // [32][256], reused after mainloop
    __shared__ float mu_s[TP];
    __shared__ float rs_s[TP];

    const float* __restrict__ shi = (STAGE == 0) ? g_xhi : g_h1hi;
    const float* __restrict__ slo = (STAGE == 0) ? g_xlo : g_h1lo;
    const float4* __restrict__ wfb = (STAGE == 0) ? g_wf1 : g_wf2;

    const int blk = blockIdx.x;
    const int n   = blk / (LL / TP);
    const int l0  = (blk % (LL / TP)) * TP;
    const int f   = threadIdx.x;
    const int wid = f >> 5, lane = f & 31;

    // Load input rows (zero padding at sequence edges)
    #pragma unroll
    for (int r = 0; r < TP + 2; r++) {
        int l = l0 - 1 + r;
        const bool ok = (l >= 0 && l < LL);
        xs_hi[r * XSS + f] = ok ? shi[(n * LL + l) * DD + f] : 0.f;
        xs_lo[r * XSS + f] = ok ? slo[(n * LL + l) * DD + f] : 0.f;
    }
    __syncthreads();

    // C fragments: 8 n8-tiles (covering 64 f) x 4 regs
    float cacc[8][4];
    #pragma unroll
    for (int tl = 0; tl < 8; tl++)
        #pragma unroll
        for (int j = 0; j < 4; j++) cacc[tl][j] = 0.f;

    const int wl = wid >> 2;           // 0/1: l-subtile of 16
    const int wfq = wid & 3;           // 0..3: f-subtile of 64
    const int g = lane >> 2;           // fragment group id
    const int t = lane & 3;            // thread-in-group

    // Mainloop over K = 3 taps x 256 d (8 per MMA step)
    #pragma unroll 1
    for (int kk = 0; kk < 3; kk++) {
        const int r0 = wl * 16 + g + kk;     // A row for this thread (output l = l0 + wl*16+g)
        const float* xh = xs_hi + r0 * XSS + t;
        const float* xl = xs_lo + r0 * XSS + t;
        #pragma unroll 2
        for (int c = 0; c < 32; c++) {
            const int d0 = 8 * c;
            // A fragment (row-major 16x8): a0(r,g | c,t) a1(r+8) a2(c t+4) a3(both)
            const unsigned ah0 = __float_as_uint(xh[d0]);
            const unsigned ah1 = __float_as_uint(xh[8 * XSS + d0]);
            const unsigned ah2 = __float_as_uint(xh[d0 + 4]);
            const unsigned ah3 = __float_as_uint(xh[8 * XSS + d0 + 4]);
            const unsigned al0 = __float_as_uint(xl[d0]);
            const unsigned al1 = __float_as_uint(xl[8 * XSS + d0]);
            const unsigned al2 = __float_as_uint(xl[d0 + 4]);
            const unsigned al3 = __float_as_uint(xl[8 * XSS + d0 + 4]);

            const float4* bp = wfb + ((kk * 32 + c) * 1024) + (wfq * 8) * 32 + lane;
            #pragma unroll
            for (int tl = 0; tl < 8; tl++) {
                const float4 b = bp[tl * 32];
                const unsigned bh0 = __float_as_uint(b.x);
                const unsigned bh1 = __float_as_uint(b.y);
                const unsigned bl0 = __float_as_uint(b.z);
                const unsigned bl1 = __float_as_uint(b.w);
                mma_tf32(cacc[tl], ah0, ah1, ah2, ah3, bh0, bh1);   // hi*hi
                mma_tf32(cacc[tl], ah0, ah1, ah2, ah3, bl0, bl1);   // hi*lo
                mma_tf32(cacc[tl], al0, al1, al2, al3, bh0, bh1);   // lo*hi
            }
        }
    }
    __syncthreads();   // all xs reads done; reuse smem as hs tile

    // Stage C fragments into hs[l][f]
    {
        const int pr0 = wl * 16 + g;
        #pragma unroll
        for (int tl = 0; tl < 8; tl++) {
            const int fc = wfq * 64 + tl * 8 + t * 2;
            *(float2*)&hs[pr0 * 256 + fc]       = make_float2(cacc[tl][0], cacc[tl][1]);
            *(float2*)&hs[(pr0 + 8) * 256 + fc] = make_float2(cacc[tl][2], cacc[tl][3]);
        }
    }
    __syncthreads();

    // Bias add (per-thread f view), keep acc in regs, rewrite hs for stats
    float acc[TP];
    {
        const float bf = bias[f];
        #pragma unroll
        for (int p = 0; p < TP; p++) {
            acc[p] = hs[p * 256 + f] + bf;
            hs[p * 256 + f] = acc[p];
        }
    }
    __syncthreads();

    // LayerNorm over f (256) per position p: warp-parallel reductions
    {
        #pragma unroll
        for (int rr = 0; rr < 4; rr++) {
            int r = wid * 4 + rr;
            float s = 0.f, s2 = 0.f;
            #pragma unroll
            for (int c0 = 0; c0 < 256; c0 += 32) {
                float v = hs[r * 256 + c0 + lane];
                s += v; s2 += v * v;
            }
            #pragma unroll
            for (int o = 16; o; o >>= 1) {
                s  += __shfl_xor_sync(0xFFFFFFFFu, s,  o);
                s2 += __shfl_xor_sync(0xFFFFFFFFu, s2, o);
            }
            if (lane == 0) {
                float mu = s * (1.f / 256.f);
                float var = s2 * (1.f / 256.f) - mu * mu;
                mu_s[r] = mu;
                rs_s[r] = rsqrtf(var + 1e-5f);
            }
        }
    }
    __syncthreads();

    if (STAGE == 0) {
        const float gg = gamma[f], bb = beta[f];
        #pragma unroll
        for (int p = 0; p < TP; p++) {
            float v = fmaxf((acc[p] - mu_s[p]) * rs_s[p] * gg + bb, 0.f);
            const unsigned hb = f2tf32(v);
            const float hf = __uint_as_float(hb);
            const unsigned lb = f2tf32(v - hf);
            g_h1hi[(n * LL + l0 + p) * DD + f] = hf;
            g_h1lo[(n * LL + l0 + p) * DD + f] = __uint_as_float(lb);
        }
    } else {
        // Fused linear head: prod[p][f] = relu(LN(h)) * lin_w[f], reduce over f.
        const float gg = gamma[f], bb = beta[f];
        const float lw = lin_w[f];
        #pragma unroll
        for (int p = 0; p < TP; p++) {
            float v = fmaxf((acc[p] - mu_s[p]) * rs_s[p] * gg + bb, 0.f);
            hs[p * 256 + f] = v * lw;
        }
        __syncthreads();
        {
            const float lb = lin_b[0];
            #pragma unroll
            for (int rr = 0; rr < 4; rr++) {
                int r = wid * 4 + rr;
                float s = 0.f;
                #pragma unroll
                for (int c0 = 0; c0 < 256; c0 += 32)
                    s += hs[r * 256 + c0 + lane];
                #pragma unroll
                for (int o = 16; o; o >>= 1)
                    s += __shfl_xor_sync(0xFFFFFFFFu, s, o);
                if (lane == 0) {
                    float dpo = fmaxf(s + lb, 0.f);
                    g_dur[n * LL + l0 + r] = (int)(dpo + 0.5f);
                }
            }
        }
    }
}

// ---------------------------------------------------------------------------
// Inclusive scan of durations per row + t -> l binary-search map.
// ---------------------------------------------------------------------------
__global__ void __launch_bounds__(512) scan_map_kernel()
{
    const int n = blockIdx.x;
    const int l = threadIdx.x;

    __shared__ int sc[LL];
    sc[l] = g_dur[n * LL + l];
    __syncthreads();
    for (int off = 1; off < LL; off <<= 1) {
        int v = (l >= off) ? sc[l - off] : 0;
        __syncthreads();
        sc[l] += v;
        __syncthreads();
    }

    const int total = sc[LL - 1];
    for (int t = l; t < TT; t += LL) {
        int res = -1;
        if (t < total) {
            int lo = 0, hi = LL - 1;
            while (lo < hi) {
                int mid = (lo + hi) >> 1;
                if (sc[mid] > t) hi = mid; else lo = mid + 1;
            }
            res = lo;
        }
        g_lmap[n * TT + t] = res;
    }
}

// ---------------------------------------------------------------------------
// out[n, t, :] = x[n, lmap[n,t], :]  (or zeros), grid-stride (8 float4/thread)
// + fused tail (WVF_pos = 1..TT). 2048 blocks.
// ---------------------------------------------------------------------------
#define EXP_BLOCKS 2048
__global__ void __launch_bounds__(256) expand_copy_kernel(
    const float* __restrict__ x,
    float* __restrict__ out,
    int tail)
{
    const int nthreads = EXP_BLOCKS * 256;
    const int tid0 = blockIdx.x * 256 + threadIdx.x;

    #pragma unroll
    for (int k = 0; k < 8; k++) {
        const int idx = tid0 + k * nthreads;       // over NB*TT*64 float4
        const int c = idx & 63;
        const int t = (idx >> 6) & (TT - 1);
        const int n = idx >> 18;
        const int l = g_lmap[n * TT + t];
        float4 v = make_float4(0.f, 0.f, 0.f, 0.f);
        if (l >= 0) v = ((const float4*)x)[(n * LL + l) * (DD / 4) + c];
        ((float4*)out)[idx] = v;
    }

    for (int i = tid0; i < tail; i += nthreads)
        out[NB * TT * DD + i] = (float)((i % TT) + 1);
}

extern "C" void kernel_launch(void* const* d_in, const int* in_sizes, int n_in,
                              void* d_out, int out_size)
{
    const float* x       = (const float*)d_in[0];
    const float* conv1_w = (const float*)d_in[1];
    const float* conv1_b = (const float*)d_in[2];
    const float* ln1_g   = (const float*)d_in[3];
    const float* ln1_b   = (const float*)d_in[4];
    const float* conv2_w = (const float*)d_in[5];
    const float* conv2_b = (const float*)d_in[6];
    const float* ln2_g   = (const float*)d_in[7];
    const float* ln2_b   = (const float*)d_in[8];
    const float* lin_w   = (const float*)d_in[9];
    const float* lin_b   = (const float*)d_in[10];

    float* out = (float*)d_out;

    // Opt-in to >48KB dynamic smem (idempotent; capture-safe; not an allocation).
    static bool attr_done = false;
    if (!attr_done) {
        cudaFuncSetAttribute(conv_ln_relu_kernel<0>,
                             cudaFuncAttributeMaxDynamicSharedMemorySize, SMEM_BYTES);
        cudaFuncSetAttribute(conv_ln_relu_kernel<1>,
                             cudaFuncAttributeMaxDynamicSharedMemorySize, SMEM_BYTES);
        attr_done = true;
    }

    prep_x_kernel<<<(NB * LL * DD) / 1024, 1024>>>(x);
    pack_wf_kernel<<<2 * 3 * 32, 1024>>>(conv1_w, conv2_w);

    const int conv_grid = NB * (LL / TP);   // 256
    conv_ln_relu_kernel<0><<<conv_grid, 256, SMEM_BYTES>>>(conv1_b, ln1_g, ln1_b, lin_w, lin_b);
    conv_ln_relu_kernel<1><<<conv_grid, 256, SMEM_BYTES>>>(conv2_b, ln2_g, ln2_b, lin_w, lin_b);
    scan_map_kernel<<<NB, LL>>>();

    const int main_elems = NB * TT * DD;
    int tail = out_size - main_elems;
    if (tail < 0) tail = 0;
    expand_copy_kernel<<<EXP_BLOCKS, 256>>>(x, out, tail);
}

// round 15
// speedup vs baseline: 1.6557x; 1.0975x over previous
#include <cuda_runtime.h>
#include <cuda_bf16.h>
#include <cstdint>

// Problem constants (fixed by setup_inputs)
#define NB 16      // batch
#define LL 512     // sequence length
#define DD 256     // encoder dim = filter size
#define TT 4096    // WVF_max_length
#define TP 32      // L-positions per conv block
#define XSS 260    // xs smem row stride (pad: 260%32=4 -> conflict-free frags)

// Intermediates (no cudaMalloc allowed) — referenced directly from device code.
__device__ float g_h1[NB * LL * DD];    // fp32 h1 (split to tf32 hi/lo on load)
__device__ int   g_dur[NB * LL];
__device__ int   g_lmap[NB * TT];
// Fragment-packed weights: [kk][c][tile][lane] float4 = (bhi0,bhi1,blo0,blo1)
//   b0 = w[kk][8c + lane%4    ][8*tile + lane/4]
//   b1 = w[kk][8c + lane%4 + 4][8*tile + lane/4]
__device__ float4 g_wf1[3 * 32 * 32 * 32];
__device__ float4 g_wf2[3 * 32 * 32 * 32];

// ---- tf32 helpers ----
__device__ __forceinline__ unsigned f2tf32(float v)
{
    unsigned r;
    asm("cvt.rna.tf32.f32 %0, %1;" : "=r"(r) : "f"(v));
    return r;
}

// m16n8k8 tf32 MMA, C += A*B (C in-place)
__device__ __forceinline__ void mma_tf32(float* c,
                                         unsigned a0, unsigned a1,
                                         unsigned a2, unsigned a3,
                                         unsigned b0, unsigned b1)
{
    asm("mma.sync.aligned.m16n8k8.row.col.f32.tf32.tf32.f32 "
        "{%0,%1,%2,%3},{%4,%5,%6,%7},{%8,%9},{%0,%1,%2,%3};"
        : "+f"(c[0]), "+f"(c[1]), "+f"(c[2]), "+f"(c[3])
        : "r"(a0), "r"(a1), "r"(a2), "r"(a3), "r"(b0), "r"(b1));
}

// ---------------------------------------------------------------------------
// Prep: pack weights into B-fragment order with tf32 hi/lo.
// grid = 2 layers * 3 kk * 32 c;  block = 1024 (tile = tid/32, lane = tid%32)
// ---------------------------------------------------------------------------
__global__ void __launch_bounds__(1024) pack_wf_kernel(
    const float* __restrict__ w1, const float* __restrict__ w2)
{
    const int b = blockIdx.x;
    const int layer = b / 96;
    const int kk = (b % 96) / 32;
    const int c = b % 32;
    const int tile = threadIdx.x >> 5;
    const int lane = threadIdx.x & 31;
    const int t = lane & 3;
    const int g = lane >> 2;
    const int f = tile * 8 + g;
    const float* src = (layer == 0) ? w1 : w2;
    float4* dst = (layer == 0) ? g_wf1 : g_wf2;

    const float w0 = src[kk * (DD * 256) + (8 * c + t) * 256 + f];
    const float w1v = src[kk * (DD * 256) + (8 * c + t + 4) * 256 + f];
    const unsigned h0 = f2tf32(w0);
    const unsigned h1 = f2tf32(w1v);
    const unsigned l0 = f2tf32(w0 - __uint_as_float(h0));
    const unsigned l1 = f2tf32(w1v - __uint_as_float(h1));
    dst[((kk * 32 + c) * 32 + tile) * 32 + lane] =
        make_float4(__uint_as_float(h0), __uint_as_float(h1),
                    __uint_as_float(l0), __uint_as_float(l1));
}

// ---------------------------------------------------------------------------
// Fused conv1d(K=3) via 3xTF32 warp-MMA + bias + LayerNorm(F) + ReLU
// STAGE 0: src = x (fp32),  dst = g_h1 (fp32)
// STAGE 1: src = g_h1 (fp32), fused linear head -> g_dur
// tf32 hi/lo split happens inline while filling smem (no prep tensors).
// Block = 32 l x 256 f, 8 warps: wl = wid>>2 (16-l subtile), wf = wid&3 (64-f).
// Dynamic smem: xs_hi[34][260] | xs_lo[34][260]; hs (32x256) aliases xs_hi.
// ---------------------------------------------------------------------------
#define SMEM_BYTES (2 * 34 * XSS * 4)   // 70720

template<int STAGE>
__global__ void __launch_bounds__(256, 2) conv_ln_relu_kernel(
    const float* __restrict__ x,
    const float* __restrict__ bias,
    const float* __restrict__ gamma,
    const float* __restrict__ beta,
    const float* __restrict__ lin_w,
    const float* __restrict__ lin_b)
{
    extern __shared__ float smem[];
    float* xs_hi = smem;                  // [34][XSS]
    float* xs_lo = smem + 34 * XSS;       // [34][XSS]
    float* hs    = smem;                  // [32][256], reused after mainloop
    __shared__ float mu_s[TP];
    __shared__ float rs_s[TP];

    const float* __restrict__ src = (STAGE == 0) ? x : (const float*)g_h1;
    const float4* __restrict__ wfb = (STAGE == 0) ? g_wf1 : g_wf2;

    const int blk = blockIdx.x;
    const int n   = blk / (LL / TP);
    const int l0  = (blk % (LL / TP)) * TP;
    const int f   = threadIdx.x;
    const int wid = f >> 5, lane = f & 31;

    // Load input rows, splitting to tf32 hi/lo inline (zero pad at edges)
    #pragma unroll
    for (int r = 0; r < TP + 2; r++) {
        int l = l0 - 1 + r;
        float v = (l >= 0 && l < LL) ? src[(n * LL + l) * DD + f] : 0.f;
        const float hf = __uint_as_float(f2tf32(v));
        xs_hi[r * XSS + f] = hf;
        xs_lo[r * XSS + f] = __uint_as_float(f2tf32(v - hf));
    }
    __syncthreads();

    // C fragments: 8 n8-tiles (covering 64 f) x 4 regs
    float cacc[8][4];
    #pragma unroll
    for (int tl = 0; tl < 8; tl++)
        #pragma unroll
        for (int j = 0; j < 4; j++) cacc[tl][j] = 0.f;

    const int wl = wid >> 2;           // 0/1: l-subtile of 16
    const int wfq = wid & 3;           // 0..3: f-subtile of 64
    const int g = lane >> 2;           // fragment group id
    const int t = lane & 3;            // thread-in-group

    // Mainloop over K = 3 taps x 256 d (8 per MMA step)
    #pragma unroll 1
    for (int kk = 0; kk < 3; kk++) {
        const int r0 = wl * 16 + g + kk;     // A row for this thread
        const float* xh = xs_hi + r0 * XSS + t;
        const float* xl = xs_lo + r0 * XSS + t;
        #pragma unroll 2
        for (int c = 0; c < 32; c++) {
            const int d0 = 8 * c;
            // A fragment (row-major 16x8)
            const unsigned ah0 = __float_as_uint(xh[d0]);
            const unsigned ah1 = __float_as_uint(xh[8 * XSS + d0]);
            const unsigned ah2 = __float_as_uint(xh[d0 + 4]);
            const unsigned ah3 = __float_as_uint(xh[8 * XSS + d0 + 4]);
            const unsigned al0 = __float_as_uint(xl[d0]);
            const unsigned al1 = __float_as_uint(xl[8 * XSS + d0]);
            const unsigned al2 = __float_as_uint(xl[d0 + 4]);
            const unsigned al3 = __float_as_uint(xl[8 * XSS + d0 + 4]);

            const float4* bp = wfb + ((kk * 32 + c) * 1024) + (wfq * 8) * 32 + lane;

            // Preload all 8 B fragments, then issue MMAs split-major:
            // consecutive MMAs target different accumulators (dep distance 8).
            float4 b[8];
            #pragma unroll
            for (int tl = 0; tl < 8; tl++) b[tl] = bp[tl * 32];
            #pragma unroll
            for (int tl = 0; tl < 8; tl++)
                mma_tf32(cacc[tl], ah0, ah1, ah2, ah3,
                         __float_as_uint(b[tl].x), __float_as_uint(b[tl].y));
            #pragma unroll
            for (int tl = 0; tl < 8; tl++)
                mma_tf32(cacc[tl], ah0, ah1, ah2, ah3,
                         __float_as_uint(b[tl].z), __float_as_uint(b[tl].w));
            #pragma unroll
            for (int tl = 0; tl < 8; tl++)
                mma_tf32(cacc[tl], al0, al1, al2, al3,
                         __float_as_uint(b[tl].x), __float_as_uint(b[tl].y));
        }
    }
    __syncthreads();   // all xs reads done; reuse smem as hs tile

    // Stage C fragments into hs[l][f]
    {
        const int pr0 = wl * 16 + g;
        #pragma unroll
        for (int tl = 0; tl < 8; tl++) {
            const int fc = wfq * 64 + tl * 8 + t * 2;
            *(float2*)&hs[pr0 * 256 + fc]       = make_float2(cacc[tl][0], cacc[tl][1]);
            *(float2*)&hs[(pr0 + 8) * 256 + fc] = make_float2(cacc[tl][2], cacc[tl][3]);
        }
    }
    __syncthreads();

    // Bias add (per-thread f view), keep acc in regs, rewrite hs for stats
    float acc[TP];
    {
        const float bf = bias[f];
        #pragma unroll
        for (int p = 0; p < TP; p++) {
            acc[p] = hs[p * 256 + f] + bf;
            hs[p * 256 + f] = acc[p];
        }
    }
    __syncthreads();

    // LayerNorm over f (256) per position p: warp-parallel reductions
    {
        #pragma unroll
        for (int rr = 0; rr < 4; rr++) {
            int r = wid * 4 + rr;
            float s = 0.f, s2 = 0.f;
            #pragma unroll
            for (int c0 = 0; c0 < 256; c0 += 32) {
                float v = hs[r * 256 + c0 + lane];
                s += v; s2 += v * v;
            }
            #pragma unroll
            for (int o = 16; o; o >>= 1) {
                s  += __shfl_xor_sync(0xFFFFFFFFu, s,  o);
                s2 += __shfl_xor_sync(0xFFFFFFFFu, s2, o);
            }
            if (lane == 0) {
                float mu = s * (1.f / 256.f);
                float var = s2 * (1.f / 256.f) - mu * mu;
                mu_s[r] = mu;
                rs_s[r] = rsqrtf(var + 1e-5f);
            }
        }
    }
    __syncthreads();

    if (STAGE == 0) {
        const float gg = gamma[f], bb = beta[f];
        #pragma unroll
        for (int p = 0; p < TP; p++) {
            float v = fmaxf((acc[p] - mu_s[p]) * rs_s[p] * gg + bb, 0.f);
            g_h1[(n * LL + l0 + p) * DD + f] = v;
        }
    } else {
        // Fused linear head: prod[p][f] = relu(LN(h)) * lin_w[f], reduce over f.
        const float gg = gamma[f], bb = beta[f];
        const float lw = lin_w[f];
        #pragma unroll
        for (int p = 0; p < TP; p++) {
            float v = fmaxf((acc[p] - mu_s[p]) * rs_s[p] * gg + bb, 0.f);
            hs[p * 256 + f] = v * lw;
        }
        __syncthreads();
        {
            const float lb = lin_b[0];
            #pragma unroll
            for (int rr = 0; rr < 4; rr++) {
                int r = wid * 4 + rr;
                float s = 0.f;
                #pragma unroll
                for (int c0 = 0; c0 < 256; c0 += 32)
                    s += hs[r * 256 + c0 + lane];
                #pragma unroll
                for (int o = 16; o; o >>= 1)
                    s += __shfl_xor_sync(0xFFFFFFFFu, s, o);
                if (lane == 0) {
                    float dpo = fmaxf(s + lb, 0.f);
                    g_dur[n * LL + l0 + r] = (int)(dpo + 0.5f);
                }
            }
        }
    }
}

// ---------------------------------------------------------------------------
// Inclusive scan of durations per row + t -> l binary-search map.
// ---------------------------------------------------------------------------
__global__ void __launch_bounds__(512) scan_map_kernel()
{
    const int n = blockIdx.x;
    const int l = threadIdx.x;

    __shared__ int sc[LL];
    sc[l] = g_dur[n * LL + l];
    __syncthreads();
    for (int off = 1; off < LL; off <<= 1) {
        int v = (l >= off) ? sc[l - off] : 0;
        __syncthreads();
        sc[l] += v;
        __syncthreads();
    }

    const int total = sc[LL - 1];
    for (int t = l; t < TT; t += LL) {
        int res = -1;
        if (t < total) {
            int lo = 0, hi = LL - 1;
            while (lo < hi) {
                int mid = (lo + hi) >> 1;
                if (sc[mid] > t) hi = mid; else lo = mid + 1;
            }
            res = lo;
        }
        g_lmap[n * TT + t] = res;
    }
}

// ---------------------------------------------------------------------------
// out[n, t, :] = x[n, lmap[n,t], :]  (or zeros), grid-stride (8 float4/thread)
// + fused tail (WVF_pos = 1..TT). 2048 blocks.
// ---------------------------------------------------------------------------
#define EXP_BLOCKS 2048
__global__ void __launch_bounds__(256) expand_copy_kernel(
    const float* __restrict__ x,
    float* __restrict__ out,
    int tail)
{
    const int nthreads = EXP_BLOCKS * 256;
    const int tid0 = blockIdx.x * 256 + threadIdx.x;

    #pragma unroll
    for (int k = 0; k < 8; k++) {
        const int idx = tid0 + k * nthreads;       // over NB*TT*64 float4
        const int c = idx & 63;
        const int t = (idx >> 6) & (TT - 1);
        const int n = idx >> 18;
        const int l = g_lmap[n * TT + t];
        float4 v = make_float4(0.f, 0.f, 0.f, 0.f);
        if (l >= 0) v = ((const float4*)x)[(n * LL + l) * (DD / 4) + c];
        ((float4*)out)[idx] = v;
    }

    for (int i = tid0; i < tail; i += nthreads)
        out[NB * TT * DD + i] = (float)((i % TT) + 1);
}

extern "C" void kernel_launch(void* const* d_in, const int* in_sizes, int n_in,
                              void* d_out, int out_size)
{
    const float* x       = (const float*)d_in[0];
    const float* conv1_w = (const float*)d_in[1];
    const float* conv1_b = (const float*)d_in[2];
    const float* ln1_g   = (const float*)d_in[3];
    const float* ln1_b   = (const float*)d_in[4];
    const float* conv2_w = (const float*)d_in[5];
    const float* conv2_b = (const float*)d_in[6];
    const float* ln2_g   = (const float*)d_in[7];
    const float* ln2_b   = (const float*)d_in[8];
    const float* lin_w   = (const float*)d_in[9];
    const float* lin_b   = (const float*)d_in[10];

    float* out = (float*)d_out;

    // Opt-in to >48KB dynamic smem (idempotent; capture-safe; not an allocation).
    static bool attr_done = false;
    if (!attr_done) {
        cudaFuncSetAttribute(conv_ln_relu_kernel<0>,
                             cudaFuncAttributeMaxDynamicSharedMemorySize, SMEM_BYTES);
        cudaFuncSetAttribute(conv_ln_relu_kernel<1>,
                             cudaFuncAttributeMaxDynamicSharedMemorySize, SMEM_BYTES);
        attr_done = true;
    }

    pack_wf_kernel<<<2 * 3 * 32, 1024>>>(conv1_w, conv2_w);

    const int conv_grid = NB * (LL / TP);   // 256
    conv_ln_relu_kernel<0><<<conv_grid, 256, SMEM_BYTES>>>(x, conv1_b, ln1_g, ln1_b, lin_w, lin_b);
    conv_ln_relu_kernel<1><<<conv_grid, 256, SMEM_BYTES>>>(x, conv2_b, ln2_g, ln2_b, lin_w, lin_b);
    scan_map_kernel<<<NB, LL>>>();

    const int main_elems = NB * TT * DD;
    int tail = out_size - main_elems;
    if (tail < 0) tail = 0;
    expand_copy_kernel<<<EXP_BLOCKS, 256>>>(x, out, tail);
}